// round 1
// baseline (speedup 1.0000x reference)
#include <cuda_runtime.h>

#define NB 16
#define NS 512
#define NE 512
#define NH 8
#define ND 64

// Scratch (device globals — no allocation allowed)
__device__ float g_Q[NB*NH*NS*ND];           // (b,h,s,d) 16MB
__device__ float g_K[NB*NH*NS*ND];
__device__ float g_V[NB*NH*NS*ND];
__device__ float g_cat[NB*NS*2*NE];          // (b*s, [Qf | attn_out]) 32MB

// ---------------------------------------------------------------------------
// Kernel 1: VQC projection. One warp per head-vector m = (b*S+s)*H + h.
// angles = x·W_in + b_in + w_layer ; z from closed-form cosine products;
// out = z·W_outT + b_out. Writes (b,h,s,d) for attention; tensor 0 also
// writes the Qf half of g_cat.
// ---------------------------------------------------------------------------
__global__ void proj_kernel(
    const float* __restrict__ Xq, const float* __restrict__ Xk, const float* __restrict__ Xv,
    const float* __restrict__ Wq_in, const float* __restrict__ bq_in,
    const float* __restrict__ Wk_in, const float* __restrict__ bk_in,
    const float* __restrict__ Wv_in, const float* __restrict__ bv_in,
    const float* __restrict__ wvq, const float* __restrict__ wvk, const float* __restrict__ wvv,
    const float* __restrict__ Wq_o, const float* __restrict__ bq_o,
    const float* __restrict__ Wk_o, const float* __restrict__ bk_o,
    const float* __restrict__ Wv_o, const float* __restrict__ bv_o)
{
    const int t = blockIdx.y;
    const float *X, *Win, *bin, *wv, *Wout, *bout;
    float* dst;
    if (t == 0)      { X=Xq; Win=Wq_in; bin=bq_in; wv=wvq; Wout=Wq_o; bout=bq_o; dst=g_Q; }
    else if (t == 1) { X=Xk; Win=Wk_in; bin=bk_in; wv=wvk; Wout=Wk_o; bout=bk_o; dst=g_K; }
    else             { X=Xv; Win=Wv_in; bin=bv_in; wv=wvv; Wout=Wv_o; bout=bv_o; dst=g_V; }

    const int lane = threadIdx.x & 31;
    const int m = blockIdx.x * 8 + (threadIdx.x >> 5);   // < 65536
    const float* x = X + (size_t)m * 64;
    const float x0 = x[lane];
    const float x1 = x[lane + 32];

    float c[4];
#pragma unroll
    for (int q = 0; q < 4; q++) {
        float p = x0 * Win[q*64 + lane] + x1 * Win[q*64 + 32 + lane];
#pragma unroll
        for (int off = 16; off; off >>= 1)
            p += __shfl_xor_sync(0xffffffffu, p, off);
        c[q] = __cosf(p + bin[q] + wv[q]);
    }
    const float z0 = c[1]*c[2]*c[3];
    const float z1 = c[0]*c[1];
    const float z2 = z1*c[2];
    const float z3 = z2*c[3];

    const int h  = m & 7;
    const int bs = m >> 3;          // b*S + s
    const int b  = bs >> 9;
    const int s  = bs & 511;
    float* drow = dst + ((size_t)(b*NH + h) * NS + s) * 64;
#pragma unroll
    for (int half = 0; half < 2; half++) {
        const int d = lane + 32*half;
        const float4 w = *(const float4*)(Wout + d*4);      // W_out row d: (D,NQ)
        const float o = z0*w.x + z1*w.y + z2*w.z + z3*w.w + bout[d];
        drow[d] = o;
        if (t == 0) g_cat[(size_t)bs*1024 + h*64 + d] = o;  // Qf half of concat
    }
}

// ---------------------------------------------------------------------------
// Kernel 2: fused flash attention (fp32). Block = one (b,h) × 64-query tile.
// 256 threads as 16x16, each owns a 4x4 fragment (strided by 16).
// scale 1/32 folded into Q at load. Mask is a genuine no-op in the reference.
// ---------------------------------------------------------------------------
struct FaSmem {
    float Qs[64][68];
    float Ks[64][68];
    float Vt[64][68];   // transposed: [d][k]
    float Ps[64][68];
};

extern __shared__ unsigned char dyn_smem[];

__global__ void __launch_bounds__(256, 1) attn_kernel()
{
    FaSmem* sm = (FaSmem*)dyn_smem;
    const int tid = threadIdx.x;
    const int tx = tid & 15, ty = tid >> 4;
    const int qt = blockIdx.x & 7;
    const int bh = blockIdx.x >> 3;

    const float* Qg = g_Q + ((size_t)bh * NS + qt*64) * 64;
    const float* Kg = g_K + (size_t)bh * NS * 64;
    const float* Vg = g_V + (size_t)bh * NS * 64;

    for (int i = tid; i < 1024; i += 256) {
        const int r = i >> 4, c4 = (i & 15) * 4;
        float4 v = *(const float4*)(Qg + r*64 + c4);
        v.x *= 0.03125f; v.y *= 0.03125f; v.z *= 0.03125f; v.w *= 0.03125f;
        *(float4*)&sm->Qs[r][c4] = v;
    }

    float mi[4], li[4], O[4][4];
#pragma unroll
    for (int i = 0; i < 4; i++) {
        mi[i] = -1e30f; li[i] = 0.f;
#pragma unroll
        for (int j = 0; j < 4; j++) O[i][j] = 0.f;
    }

    for (int kt = 0; kt < 8; kt++) {
        __syncthreads();   // prior PV reads of Ps/Vt done before overwrite
        const float* Kt  = Kg + kt*64*64;
        const float* Vtg = Vg + kt*64*64;
        for (int i = tid; i < 1024; i += 256) {
            const int r = i >> 4, c4 = (i & 15) * 4;
            *(float4*)&sm->Ks[r][c4] = *(const float4*)(Kt + r*64 + c4);
            float4 w = *(const float4*)(Vtg + r*64 + c4);
            sm->Vt[c4+0][r] = w.x; sm->Vt[c4+1][r] = w.y;
            sm->Vt[c4+2][r] = w.z; sm->Vt[c4+3][r] = w.w;
        }
        __syncthreads();

        // ---- S = Q·K^T (64x64) ----
        float sc[4][4];
#pragma unroll
        for (int i = 0; i < 4; i++)
#pragma unroll
            for (int j = 0; j < 4; j++) sc[i][j] = 0.f;
#pragma unroll
        for (int d = 0; d < 64; d += 4) {
            float4 a[4], bb[4];
#pragma unroll
            for (int i = 0; i < 4; i++) a[i]  = *(const float4*)&sm->Qs[ty + 16*i][d];
#pragma unroll
            for (int j = 0; j < 4; j++) bb[j] = *(const float4*)&sm->Ks[tx + 16*j][d];
#pragma unroll
            for (int i = 0; i < 4; i++)
#pragma unroll
                for (int j = 0; j < 4; j++)
                    sc[i][j] += a[i].x*bb[j].x + a[i].y*bb[j].y
                              + a[i].z*bb[j].z + a[i].w*bb[j].w;
        }

        // ---- online softmax (rows distributed over the 16 tx lanes) ----
#pragma unroll
        for (int i = 0; i < 4; i++) {
            float mt = fmaxf(fmaxf(sc[i][0], sc[i][1]), fmaxf(sc[i][2], sc[i][3]));
#pragma unroll
            for (int off = 8; off; off >>= 1)
                mt = fmaxf(mt, __shfl_xor_sync(0xffffffffu, mt, off));
            const float nm = fmaxf(mi[i], mt);
            const float f  = __expf(mi[i] - nm);
            mi[i] = nm;
            float ls = 0.f;
#pragma unroll
            for (int j = 0; j < 4; j++) { sc[i][j] = __expf(sc[i][j] - nm); ls += sc[i][j]; }
#pragma unroll
            for (int off = 8; off; off >>= 1)
                ls += __shfl_xor_sync(0xffffffffu, ls, off);
            li[i] = li[i]*f + ls;
#pragma unroll
            for (int j = 0; j < 4; j++) O[i][j] *= f;
        }
#pragma unroll
        for (int i = 0; i < 4; i++)
#pragma unroll
            for (int j = 0; j < 4; j++)
                sm->Ps[ty + 16*i][tx + 16*j] = sc[i][j];
        __syncthreads();

        // ---- O += P·V (64x64x64) ----
#pragma unroll
        for (int k = 0; k < 64; k += 4) {
            float4 a[4], bb[4];
#pragma unroll
            for (int i = 0; i < 4; i++) a[i]  = *(const float4*)&sm->Ps[ty + 16*i][k];
#pragma unroll
            for (int j = 0; j < 4; j++) bb[j] = *(const float4*)&sm->Vt[tx + 16*j][k];
#pragma unroll
            for (int i = 0; i < 4; i++)
#pragma unroll
                for (int j = 0; j < 4; j++)
                    O[i][j] += a[i].x*bb[j].x + a[i].y*bb[j].y
                             + a[i].z*bb[j].z + a[i].w*bb[j].w;
        }
    }

    const int b = bh >> 3, h = bh & 7;
#pragma unroll
    for (int i = 0; i < 4; i++) {
        const int q = qt*64 + ty + 16*i;
        const float inv = 1.f / li[i];
        float* orow = g_cat + (size_t)(b*NS + q)*1024 + 512 + h*64;
#pragma unroll
        for (int j = 0; j < 4; j++)
            orow[tx + 16*j] = O[i][j] * inv;
    }
}

// ---------------------------------------------------------------------------
// Kernel 3: out = cat(8192x1024) @ Wo^T(1024x512) + bo.  NT GEMM, 64x64 tile.
// ---------------------------------------------------------------------------
__global__ void __launch_bounds__(256) outproj_kernel(
    const float* __restrict__ Wo, const float* __restrict__ bo,
    float* __restrict__ out)
{
    __shared__ float As[64][68];
    __shared__ float Bs[64][68];
    const int tid = threadIdx.x;
    const int tx = tid & 15, ty = tid >> 4;
    const int n0 = blockIdx.x * 64;
    const int e0 = blockIdx.y * 64;

    float acc[4][4];
#pragma unroll
    for (int i = 0; i < 4; i++)
#pragma unroll
        for (int j = 0; j < 4; j++) acc[i][j] = 0.f;

    for (int kt = 0; kt < 16; kt++) {
        __syncthreads();
        for (int i = tid; i < 1024; i += 256) {
            const int r = i >> 4, c4 = (i & 15) * 4;
            *(float4*)&As[r][c4] = *(const float4*)(g_cat + (size_t)(n0 + r)*1024 + kt*64 + c4);
            *(float4*)&Bs[r][c4] = *(const float4*)(Wo    + (size_t)(e0 + r)*1024 + kt*64 + c4);
        }
        __syncthreads();
#pragma unroll
        for (int d = 0; d < 64; d += 4) {
            float4 a[4], bb[4];
#pragma unroll
            for (int i = 0; i < 4; i++) a[i]  = *(const float4*)&As[ty + 16*i][d];
#pragma unroll
            for (int j = 0; j < 4; j++) bb[j] = *(const float4*)&Bs[tx + 16*j][d];
#pragma unroll
            for (int i = 0; i < 4; i++)
#pragma unroll
                for (int j = 0; j < 4; j++)
                    acc[i][j] += a[i].x*bb[j].x + a[i].y*bb[j].y
                               + a[i].z*bb[j].z + a[i].w*bb[j].w;
        }
    }

#pragma unroll
    for (int i = 0; i < 4; i++) {
        const int n = n0 + ty + 16*i;
#pragma unroll
        for (int j = 0; j < 4; j++) {
            const int e = e0 + tx + 16*j;
            out[(size_t)n*512 + e] = acc[i][j] + bo[e];
        }
    }
}

// ---------------------------------------------------------------------------
extern "C" void kernel_launch(void* const* d_in, const int* in_sizes, int n_in,
                              void* d_out, int out_size)
{
    const float* query = (const float*)d_in[0];
    const float* key   = (const float*)d_in[1];
    const float* value = (const float*)d_in[2];
    // d_in[3]: mask (int32) — provably a no-op in the reference
    const float* Wq_in = (const float*)d_in[4];
    const float* bq_in = (const float*)d_in[5];
    const float* Wk_in = (const float*)d_in[6];
    const float* bk_in = (const float*)d_in[7];
    const float* Wv_in = (const float*)d_in[8];
    const float* bv_in = (const float*)d_in[9];
    const float* wvq   = (const float*)d_in[10];
    const float* wvk   = (const float*)d_in[11];
    const float* wvv   = (const float*)d_in[12];
    const float* Wq_o  = (const float*)d_in[13];
    const float* bq_o  = (const float*)d_in[14];
    const float* Wk_o  = (const float*)d_in[15];
    const float* bk_o  = (const float*)d_in[16];
    const float* Wv_o  = (const float*)d_in[17];
    const float* bv_o  = (const float*)d_in[18];
    const float* Wo    = (const float*)d_in[19];
    const float* bo    = (const float*)d_in[20];
    float* out = (float*)d_out;

    cudaFuncSetAttribute(attn_kernel, cudaFuncAttributeMaxDynamicSharedMemorySize,
                         (int)sizeof(FaSmem));

    // K1: VQC projections (Q,K,V), 65536 warps per tensor
    proj_kernel<<<dim3(8192, 3), 256>>>(query, key, value,
                                        Wq_in, bq_in, Wk_in, bk_in, Wv_in, bv_in,
                                        wvq, wvk, wvv,
                                        Wq_o, bq_o, Wk_o, bk_o, Wv_o, bv_o);
    // K2: fused attention, 16*8 heads x 8 query tiles
    attn_kernel<<<1024, 256, sizeof(FaSmem)>>>();
    // K3: final projection
    outproj_kernel<<<dim3(128, 8), 256>>>(Wo, bo, out);
}

// round 3
// speedup vs baseline: 1.4559x; 1.4559x over previous
#include <cuda_runtime.h>
#include <cstdint>

#define NB 16
#define NS 512
#define NE 512
#define NH 8
#define ND 64

// Scratch (device globals — no allocation allowed)
__device__ float g_Q[NB*NH*NS*ND];           // (b,h,s,d) 16MB
__device__ float g_K[NB*NH*NS*ND];
__device__ float g_V[NB*NH*NS*ND];
__device__ float g_cat[NB*NS*2*NE];          // (b*s, [Qf | attn_out]) 32MB

__device__ __forceinline__ uint32_t f2tf32(float f) {
    uint32_t r;
    asm("cvt.rna.tf32.f32 %0, %1;" : "=r"(r) : "f"(f));
    return r;
}

// mma.sync m16n8k8 tf32: D = A*B + D (f32 accum)
__device__ __forceinline__ void mma_tf32(float* c, const uint32_t* a, const uint32_t* b)
{
    asm volatile(
        "mma.sync.aligned.m16n8k8.row.col.f32.tf32.tf32.f32 "
        "{%0,%1,%2,%3}, {%4,%5,%6,%7}, {%8,%9}, {%0,%1,%2,%3};"
        : "+f"(c[0]), "+f"(c[1]), "+f"(c[2]), "+f"(c[3])
        : "r"(a[0]), "r"(a[1]), "r"(a[2]), "r"(a[3]), "r"(b[0]), "r"(b[1]));
}

// ---------------------------------------------------------------------------
// Kernel 1: VQC projection (unchanged, known good).
// ---------------------------------------------------------------------------
__global__ void proj_kernel(
    const float* __restrict__ Xq, const float* __restrict__ Xk, const float* __restrict__ Xv,
    const float* __restrict__ Wq_in, const float* __restrict__ bq_in,
    const float* __restrict__ Wk_in, const float* __restrict__ bk_in,
    const float* __restrict__ Wv_in, const float* __restrict__ bv_in,
    const float* __restrict__ wvq, const float* __restrict__ wvk, const float* __restrict__ wvv,
    const float* __restrict__ Wq_o, const float* __restrict__ bq_o,
    const float* __restrict__ Wk_o, const float* __restrict__ bk_o,
    const float* __restrict__ Wv_o, const float* __restrict__ bv_o)
{
    const int t = blockIdx.y;
    const float *X, *Win, *bin, *wv, *Wout, *bout;
    float* dst;
    if (t == 0)      { X=Xq; Win=Wq_in; bin=bq_in; wv=wvq; Wout=Wq_o; bout=bq_o; dst=g_Q; }
    else if (t == 1) { X=Xk; Win=Wk_in; bin=bk_in; wv=wvk; Wout=Wk_o; bout=bk_o; dst=g_K; }
    else             { X=Xv; Win=Wv_in; bin=bv_in; wv=wvv; Wout=Wv_o; bout=bv_o; dst=g_V; }

    const int lane = threadIdx.x & 31;
    const int m = blockIdx.x * 8 + (threadIdx.x >> 5);
    const float* x = X + (size_t)m * 64;
    const float x0 = x[lane];
    const float x1 = x[lane + 32];

    float c[4];
#pragma unroll
    for (int q = 0; q < 4; q++) {
        float p = x0 * Win[q*64 + lane] + x1 * Win[q*64 + 32 + lane];
#pragma unroll
        for (int off = 16; off; off >>= 1)
            p += __shfl_xor_sync(0xffffffffu, p, off);
        c[q] = __cosf(p + bin[q] + wv[q]);
    }
    const float z0 = c[1]*c[2]*c[3];
    const float z1 = c[0]*c[1];
    const float z2 = z1*c[2];
    const float z3 = z2*c[3];

    const int h  = m & 7;
    const int bs = m >> 3;
    const int b  = bs >> 9;
    const int s  = bs & 511;
    float* drow = dst + ((size_t)(b*NH + h) * NS + s) * 64;
#pragma unroll
    for (int half = 0; half < 2; half++) {
        const int d = lane + 32*half;
        const float4 w = *(const float4*)(Wout + d*4);
        const float o = z0*w.x + z1*w.y + z2*w.z + z3*w.w + bout[d];
        drow[d] = o;
        if (t == 0) g_cat[(size_t)bs*1024 + h*64 + d] = o;
    }
}

// ---------------------------------------------------------------------------
// Kernel 2: fused flash attention fp32 (unchanged, known good).
// ---------------------------------------------------------------------------
struct FaSmem {
    float Qs[64][68];
    float Ks[64][68];
    float Vt[64][68];
    float Ps[64][68];
};

extern __shared__ unsigned char dyn_smem[];

__global__ void __launch_bounds__(256, 1) attn_kernel()
{
    FaSmem* sm = (FaSmem*)dyn_smem;
    const int tid = threadIdx.x;
    const int tx = tid & 15, ty = tid >> 4;
    const int qt = blockIdx.x & 7;
    const int bh = blockIdx.x >> 3;

    const float* Qg = g_Q + ((size_t)bh * NS + qt*64) * 64;
    const float* Kg = g_K + (size_t)bh * NS * 64;
    const float* Vg = g_V + (size_t)bh * NS * 64;

    for (int i = tid; i < 1024; i += 256) {
        const int r = i >> 4, c4 = (i & 15) * 4;
        float4 v = *(const float4*)(Qg + r*64 + c4);
        v.x *= 0.03125f; v.y *= 0.03125f; v.z *= 0.03125f; v.w *= 0.03125f;
        *(float4*)&sm->Qs[r][c4] = v;
    }

    float mi[4], li[4], O[4][4];
#pragma unroll
    for (int i = 0; i < 4; i++) {
        mi[i] = -1e30f; li[i] = 0.f;
#pragma unroll
        for (int j = 0; j < 4; j++) O[i][j] = 0.f;
    }

    for (int kt = 0; kt < 8; kt++) {
        __syncthreads();
        const float* Kt  = Kg + kt*64*64;
        const float* Vtg = Vg + kt*64*64;
        for (int i = tid; i < 1024; i += 256) {
            const int r = i >> 4, c4 = (i & 15) * 4;
            *(float4*)&sm->Ks[r][c4] = *(const float4*)(Kt + r*64 + c4);
            float4 w = *(const float4*)(Vtg + r*64 + c4);
            sm->Vt[c4+0][r] = w.x; sm->Vt[c4+1][r] = w.y;
            sm->Vt[c4+2][r] = w.z; sm->Vt[c4+3][r] = w.w;
        }
        __syncthreads();

        float sc[4][4];
#pragma unroll
        for (int i = 0; i < 4; i++)
#pragma unroll
            for (int j = 0; j < 4; j++) sc[i][j] = 0.f;
#pragma unroll
        for (int d = 0; d < 64; d += 4) {
            float4 a[4], bb[4];
#pragma unroll
            for (int i = 0; i < 4; i++) a[i]  = *(const float4*)&sm->Qs[ty + 16*i][d];
#pragma unroll
            for (int j = 0; j < 4; j++) bb[j] = *(const float4*)&sm->Ks[tx + 16*j][d];
#pragma unroll
            for (int i = 0; i < 4; i++)
#pragma unroll
                for (int j = 0; j < 4; j++)
                    sc[i][j] += a[i].x*bb[j].x + a[i].y*bb[j].y
                              + a[i].z*bb[j].z + a[i].w*bb[j].w;
        }

#pragma unroll
        for (int i = 0; i < 4; i++) {
            float mt = fmaxf(fmaxf(sc[i][0], sc[i][1]), fmaxf(sc[i][2], sc[i][3]));
#pragma unroll
            for (int off = 8; off; off >>= 1)
                mt = fmaxf(mt, __shfl_xor_sync(0xffffffffu, mt, off));
            const float nm = fmaxf(mi[i], mt);
            const float f  = __expf(mi[i] - nm);
            mi[i] = nm;
            float ls = 0.f;
#pragma unroll
            for (int j = 0; j < 4; j++) { sc[i][j] = __expf(sc[i][j] - nm); ls += sc[i][j]; }
#pragma unroll
            for (int off = 8; off; off >>= 1)
                ls += __shfl_xor_sync(0xffffffffu, ls, off);
            li[i] = li[i]*f + ls;
#pragma unroll
            for (int j = 0; j < 4; j++) O[i][j] *= f;
        }
#pragma unroll
        for (int i = 0; i < 4; i++)
#pragma unroll
            for (int j = 0; j < 4; j++)
                sm->Ps[ty + 16*i][tx + 16*j] = sc[i][j];
        __syncthreads();

#pragma unroll
        for (int k = 0; k < 64; k += 4) {
            float4 a[4], bb[4];
#pragma unroll
            for (int i = 0; i < 4; i++) a[i]  = *(const float4*)&sm->Ps[ty + 16*i][k];
#pragma unroll
            for (int j = 0; j < 4; j++) bb[j] = *(const float4*)&sm->Vt[tx + 16*j][k];
#pragma unroll
            for (int i = 0; i < 4; i++)
#pragma unroll
                for (int j = 0; j < 4; j++)
                    O[i][j] += a[i].x*bb[j].x + a[i].y*bb[j].y
                             + a[i].z*bb[j].z + a[i].w*bb[j].w;
        }
    }

    const int b = bh >> 3, h = bh & 7;
#pragma unroll
    for (int i = 0; i < 4; i++) {
        const int q = qt*64 + ty + 16*i;
        const float inv = 1.f / li[i];
        float* orow = g_cat + (size_t)(b*NS + q)*1024 + 512 + h*64;
#pragma unroll
        for (int j = 0; j < 4; j++)
            orow[tx + 16*j] = O[i][j] * inv;
    }
}

// ---------------------------------------------------------------------------
// Kernel 3: out = cat(8192x1024) @ Wo^T + bo via mma.sync tf32 (m16n8k8).
// 128x128 tile, 8 warps (2x4), warp tile 64x32; K-chunks of 32.
// Smem rows padded to 36 words -> conflict-free fragment LDS.32.
// ---------------------------------------------------------------------------
__global__ void __launch_bounds__(256, 2) outproj_kernel(
    const float* __restrict__ Wo, const float* __restrict__ bo,
    float* __restrict__ out)
{
    __shared__ uint32_t As[128][36];
    __shared__ uint32_t Bs[128][36];
    const int tid  = threadIdx.x;
    const int lane = tid & 31;
    const int wid  = tid >> 5;
    const int wm   = wid >> 2;      // 0..1
    const int wn   = wid & 3;       // 0..3
    const int g    = lane >> 2;     // 0..7
    const int t    = lane & 3;      // 0..3
    const int m0   = blockIdx.x * 128;
    const int e0   = blockIdx.y * 128;

    float acc[4][4][4];
#pragma unroll
    for (int mf = 0; mf < 4; mf++)
#pragma unroll
        for (int nf = 0; nf < 4; nf++)
#pragma unroll
            for (int r = 0; r < 4; r++) acc[mf][nf][r] = 0.f;

    for (int kt = 0; kt < 32; kt++) {
        __syncthreads();
        const float* Ak = g_cat + (size_t)m0 * 1024 + kt * 32;
        const float* Bk = Wo    + (size_t)e0 * 1024 + kt * 32;
#pragma unroll
        for (int it = 0; it < 4; it++) {
            const int idx = it * 256 + tid;         // 1024 float4 slots
            const int r = idx >> 3, c4 = (idx & 7) * 4;
            float4 a = *(const float4*)(Ak + (size_t)r * 1024 + c4);
            uint4 ua = { f2tf32(a.x), f2tf32(a.y), f2tf32(a.z), f2tf32(a.w) };
            *(uint4*)&As[r][c4] = ua;
            float4 b = *(const float4*)(Bk + (size_t)r * 1024 + c4);
            uint4 ub = { f2tf32(b.x), f2tf32(b.y), f2tf32(b.z), f2tf32(b.w) };
            *(uint4*)&Bs[r][c4] = ub;
        }
        __syncthreads();

#pragma unroll
        for (int ks = 0; ks < 4; ks++) {
            const int k0 = ks * 8;
            uint32_t a[4][4], b[4][2];
#pragma unroll
            for (int mf = 0; mf < 4; mf++) {
                const int rb = wm * 64 + mf * 16;
                a[mf][0] = As[rb + g    ][k0 + t    ];
                a[mf][1] = As[rb + g + 8][k0 + t    ];
                a[mf][2] = As[rb + g    ][k0 + t + 4];
                a[mf][3] = As[rb + g + 8][k0 + t + 4];
            }
#pragma unroll
            for (int nf = 0; nf < 4; nf++) {
                const int nb = wn * 32 + nf * 8;
                b[nf][0] = Bs[nb + g][k0 + t    ];
                b[nf][1] = Bs[nb + g][k0 + t + 4];
            }
#pragma unroll
            for (int mf = 0; mf < 4; mf++)
#pragma unroll
                for (int nf = 0; nf < 4; nf++)
                    mma_tf32(acc[mf][nf], a[mf], b[nf]);
        }
    }

    // epilogue: C frag rows g, g+8 ; cols 2t, 2t+1
#pragma unroll
    for (int mf = 0; mf < 4; mf++) {
        const int r0 = m0 + wm * 64 + mf * 16 + g;
#pragma unroll
        for (int nf = 0; nf < 4; nf++) {
            const int cc = e0 + wn * 32 + nf * 8 + 2 * t;
            const float b0 = bo[cc], b1 = bo[cc + 1];
            float2 v0 = { acc[mf][nf][0] + b0, acc[mf][nf][1] + b1 };
            float2 v1 = { acc[mf][nf][2] + b0, acc[mf][nf][3] + b1 };
            *(float2*)(out + (size_t)r0 * 512 + cc)       = v0;
            *(float2*)(out + (size_t)(r0 + 8) * 512 + cc) = v1;
        }
    }
}

// ---------------------------------------------------------------------------
extern "C" void kernel_launch(void* const* d_in, const int* in_sizes, int n_in,
                              void* d_out, int out_size)
{
    const float* query = (const float*)d_in[0];
    const float* key   = (const float*)d_in[1];
    const float* value = (const float*)d_in[2];
    // d_in[3]: mask (int32) — no-op in the reference
    const float* Wq_in = (const float*)d_in[4];
    const float* bq_in = (const float*)d_in[5];
    const float* Wk_in = (const float*)d_in[6];
    const float* bk_in = (const float*)d_in[7];
    const float* Wv_in = (const float*)d_in[8];
    const float* bv_in = (const float*)d_in[9];
    const float* wvq   = (const float*)d_in[10];
    const float* wvk   = (const float*)d_in[11];
    const float* wvv   = (const float*)d_in[12];
    const float* Wq_o  = (const float*)d_in[13];
    const float* bq_o  = (const float*)d_in[14];
    const float* Wk_o  = (const float*)d_in[15];
    const float* bk_o  = (const float*)d_in[16];
    const float* Wv_o  = (const float*)d_in[17];
    const float* bv_o  = (const float*)d_in[18];
    const float* Wo    = (const float*)d_in[19];
    const float* bo    = (const float*)d_in[20];
    float* out = (float*)d_out;

    cudaFuncSetAttribute(attn_kernel, cudaFuncAttributeMaxDynamicSharedMemorySize,
                         (int)sizeof(FaSmem));

    proj_kernel<<<dim3(8192, 3), 256>>>(query, key, value,
                                        Wq_in, bq_in, Wk_in, bk_in, Wv_in, bv_in,
                                        wvq, wvk, wvv,
                                        Wq_o, bq_o, Wk_o, bk_o, Wv_o, bv_o);
    attn_kernel<<<1024, 256, sizeof(FaSmem)>>>();
    outproj_kernel<<<dim3(64, 4), 256>>>(Wo, bo, out);
}

// round 4
// speedup vs baseline: 2.4242x; 1.6652x over previous
#include <cuda_runtime.h>
#include <cstdint>

#define NB 16
#define NS 512
#define NE 512
#define NH 8
#define ND 64

// Scratch (device globals — no allocation allowed)
__device__ float g_Q[NB*NH*NS*ND];           // (b,h,s,d) 16MB
__device__ float g_K[NB*NH*NS*ND];
__device__ float g_V[NB*NH*NS*ND];
__device__ float g_cat[NB*NS*2*NE];          // (b*s, [Qf | attn_out]) 32MB

__device__ __forceinline__ uint32_t f2tf32(float f) {
    uint32_t r;
    asm("cvt.rna.tf32.f32 %0, %1;" : "=r"(r) : "f"(f));
    return r;
}

// mma.sync m16n8k8 tf32: D = A*B + D (f32 accum)
__device__ __forceinline__ void mma_tf32(float* c, const uint32_t* a, const uint32_t* b)
{
    asm volatile(
        "mma.sync.aligned.m16n8k8.row.col.f32.tf32.tf32.f32 "
        "{%0,%1,%2,%3}, {%4,%5,%6,%7}, {%8,%9}, {%0,%1,%2,%3};"
        : "+f"(c[0]), "+f"(c[1]), "+f"(c[2]), "+f"(c[3])
        : "r"(a[0]), "r"(a[1]), "r"(a[2]), "r"(a[3]), "r"(b[0]), "r"(b[1]));
}

// ---------------------------------------------------------------------------
// Kernel 1: VQC projection (unchanged, known good).
// ---------------------------------------------------------------------------
__global__ void proj_kernel(
    const float* __restrict__ Xq, const float* __restrict__ Xk, const float* __restrict__ Xv,
    const float* __restrict__ Wq_in, const float* __restrict__ bq_in,
    const float* __restrict__ Wk_in, const float* __restrict__ bk_in,
    const float* __restrict__ Wv_in, const float* __restrict__ bv_in,
    const float* __restrict__ wvq, const float* __restrict__ wvk, const float* __restrict__ wvv,
    const float* __restrict__ Wq_o, const float* __restrict__ bq_o,
    const float* __restrict__ Wk_o, const float* __restrict__ bk_o,
    const float* __restrict__ Wv_o, const float* __restrict__ bv_o)
{
    const int t = blockIdx.y;
    const float *X, *Win, *bin, *wv, *Wout, *bout;
    float* dst;
    if (t == 0)      { X=Xq; Win=Wq_in; bin=bq_in; wv=wvq; Wout=Wq_o; bout=bq_o; dst=g_Q; }
    else if (t == 1) { X=Xk; Win=Wk_in; bin=bk_in; wv=wvk; Wout=Wk_o; bout=bk_o; dst=g_K; }
    else             { X=Xv; Win=Wv_in; bin=bv_in; wv=wvv; Wout=Wv_o; bout=bv_o; dst=g_V; }

    const int lane = threadIdx.x & 31;
    const int m = blockIdx.x * 8 + (threadIdx.x >> 5);
    const float* x = X + (size_t)m * 64;
    const float x0 = x[lane];
    const float x1 = x[lane + 32];

    float c[4];
#pragma unroll
    for (int q = 0; q < 4; q++) {
        float p = x0 * Win[q*64 + lane] + x1 * Win[q*64 + 32 + lane];
#pragma unroll
        for (int off = 16; off; off >>= 1)
            p += __shfl_xor_sync(0xffffffffu, p, off);
        c[q] = __cosf(p + bin[q] + wv[q]);
    }
    const float z0 = c[1]*c[2]*c[3];
    const float z1 = c[0]*c[1];
    const float z2 = z1*c[2];
    const float z3 = z2*c[3];

    const int h  = m & 7;
    const int bs = m >> 3;
    const int b  = bs >> 9;
    const int s  = bs & 511;
    float* drow = dst + ((size_t)(b*NH + h) * NS + s) * 64;
#pragma unroll
    for (int half = 0; half < 2; half++) {
        const int d = lane + 32*half;
        const float4 w = *(const float4*)(Wout + d*4);
        const float o = z0*w.x + z1*w.y + z2*w.z + z3*w.w + bout[d];
        drow[d] = o;
        if (t == 0) g_cat[(size_t)bs*1024 + h*64 + d] = o;
    }
}

// ---------------------------------------------------------------------------
// Kernel 2 (NEW): flash attention via tf32 mma.sync.
// Block: 128 queries x one (b,h). 8 warps, each owns a 16-row strip and all
// 64 kv columns of the tile (8 m16n8 n-tiles). Softmax fully in registers
// (intra-quad shfl). P staging in smem is warp-private -> __syncwarp only.
// ---------------------------------------------------------------------------
struct AtSmem {
    uint32_t Qs[128][68];   // tf32(q/32)
    uint32_t Ks[64][68];    // tf32 K tile  [key][d]
    uint32_t Vt[64][68];    // tf32 V^T     [d][key]
    uint32_t Ps[128][68];   // tf32 P tile  [q][key]
};

extern __shared__ unsigned char dyn_smem[];

__global__ void __launch_bounds__(256, 1) attn_kernel()
{
    AtSmem* sm = (AtSmem*)dyn_smem;
    const int tid  = threadIdx.x;
    const int lane = tid & 31;
    const int wid  = tid >> 5;
    const int g    = lane >> 2;     // 0..7
    const int t    = lane & 3;      // 0..3
    const int rb   = wid * 16;      // warp row strip
    const int qt   = blockIdx.x & 3;
    const int bh   = blockIdx.x >> 2;

    const float* Qg = g_Q + ((size_t)bh * NS + qt*128) * 64;
    const float* Kg = g_K + (size_t)bh * NS * 64;
    const float* Vg = g_V + (size_t)bh * NS * 64;

    // Q tile: 128x64, scale 1/32 + tf32 convert
#pragma unroll
    for (int it = 0; it < 8; it++) {
        const int idx = it * 256 + tid;
        const int r = idx >> 4, c4 = (idx & 15) * 4;
        float4 v = *(const float4*)(Qg + (size_t)r * 64 + c4);
        uint4 u = { f2tf32(v.x * 0.03125f), f2tf32(v.y * 0.03125f),
                    f2tf32(v.z * 0.03125f), f2tf32(v.w * 0.03125f) };
        *(uint4*)&sm->Qs[r][c4] = u;
    }

    float m0 = -1e30f, m1 = -1e30f, l0 = 0.f, l1 = 0.f;
    float oacc[8][4];
#pragma unroll
    for (int d = 0; d < 8; d++)
#pragma unroll
        for (int r = 0; r < 4; r++) oacc[d][r] = 0.f;

    for (int kt = 0; kt < 8; kt++) {
        __syncthreads();
        const float* Kt  = Kg + kt * 64 * 64;
        const float* Vtg = Vg + kt * 64 * 64;
#pragma unroll
        for (int it = 0; it < 4; it++) {
            const int idx = it * 256 + tid;
            const int r = idx >> 4, c4 = (idx & 15) * 4;
            float4 kk = *(const float4*)(Kt + (size_t)r * 64 + c4);
            uint4 uk = { f2tf32(kk.x), f2tf32(kk.y), f2tf32(kk.z), f2tf32(kk.w) };
            *(uint4*)&sm->Ks[r][c4] = uk;
            float4 vv = *(const float4*)(Vtg + (size_t)r * 64 + c4);
            sm->Vt[c4+0][r] = f2tf32(vv.x);
            sm->Vt[c4+1][r] = f2tf32(vv.y);
            sm->Vt[c4+2][r] = f2tf32(vv.z);
            sm->Vt[c4+3][r] = f2tf32(vv.w);
        }
        __syncthreads();

        // ---- S = Q K^T : warp strip 16 x 64 ----
        float sacc[8][4];
#pragma unroll
        for (int nt = 0; nt < 8; nt++)
#pragma unroll
            for (int r = 0; r < 4; r++) sacc[nt][r] = 0.f;
#pragma unroll
        for (int ks = 0; ks < 8; ks++) {
            const int k0 = ks * 8;
            uint32_t a[4];
            a[0] = sm->Qs[rb + g    ][k0 + t    ];
            a[1] = sm->Qs[rb + g + 8][k0 + t    ];
            a[2] = sm->Qs[rb + g    ][k0 + t + 4];
            a[3] = sm->Qs[rb + g + 8][k0 + t + 4];
#pragma unroll
            for (int nt = 0; nt < 8; nt++) {
                uint32_t b[2];
                b[0] = sm->Ks[nt*8 + g][k0 + t    ];
                b[1] = sm->Ks[nt*8 + g][k0 + t + 4];
                mma_tf32(sacc[nt], a, b);
            }
        }

        // ---- online softmax in registers (rows g and g+8) ----
        float mt0 = -1e30f, mt1 = -1e30f;
#pragma unroll
        for (int nt = 0; nt < 8; nt++) {
            mt0 = fmaxf(mt0, fmaxf(sacc[nt][0], sacc[nt][1]));
            mt1 = fmaxf(mt1, fmaxf(sacc[nt][2], sacc[nt][3]));
        }
        mt0 = fmaxf(mt0, __shfl_xor_sync(0xffffffffu, mt0, 1));
        mt0 = fmaxf(mt0, __shfl_xor_sync(0xffffffffu, mt0, 2));
        mt1 = fmaxf(mt1, __shfl_xor_sync(0xffffffffu, mt1, 1));
        mt1 = fmaxf(mt1, __shfl_xor_sync(0xffffffffu, mt1, 2));

        const float nm0 = fmaxf(m0, mt0);
        const float nm1 = fmaxf(m1, mt1);
        const float f0 = __expf(m0 - nm0);
        const float f1 = __expf(m1 - nm1);
        m0 = nm0; m1 = nm1;

        float ls0 = 0.f, ls1 = 0.f;
#pragma unroll
        for (int nt = 0; nt < 8; nt++) {
            sacc[nt][0] = __expf(sacc[nt][0] - nm0);
            sacc[nt][1] = __expf(sacc[nt][1] - nm0);
            sacc[nt][2] = __expf(sacc[nt][2] - nm1);
            sacc[nt][3] = __expf(sacc[nt][3] - nm1);
            ls0 += sacc[nt][0] + sacc[nt][1];
            ls1 += sacc[nt][2] + sacc[nt][3];
        }
        ls0 += __shfl_xor_sync(0xffffffffu, ls0, 1);
        ls0 += __shfl_xor_sync(0xffffffffu, ls0, 2);
        ls1 += __shfl_xor_sync(0xffffffffu, ls1, 1);
        ls1 += __shfl_xor_sync(0xffffffffu, ls1, 2);
        l0 = l0 * f0 + ls0;
        l1 = l1 * f1 + ls1;
#pragma unroll
        for (int d = 0; d < 8; d++) {
            oacc[d][0] *= f0; oacc[d][1] *= f0;
            oacc[d][2] *= f1; oacc[d][3] *= f1;
        }

        // stage P (warp-private rows) as tf32
#pragma unroll
        for (int nt = 0; nt < 8; nt++) {
            uint2 p0 = { f2tf32(sacc[nt][0]), f2tf32(sacc[nt][1]) };
            uint2 p1 = { f2tf32(sacc[nt][2]), f2tf32(sacc[nt][3]) };
            *(uint2*)&sm->Ps[rb + g    ][nt*8 + 2*t] = p0;
            *(uint2*)&sm->Ps[rb + g + 8][nt*8 + 2*t] = p1;
        }
        __syncwarp();

        // ---- O += P V : A = P (16x64), B = Vt ----
#pragma unroll
        for (int ks = 0; ks < 8; ks++) {
            const int k0 = ks * 8;
            uint32_t a[4];
            a[0] = sm->Ps[rb + g    ][k0 + t    ];
            a[1] = sm->Ps[rb + g + 8][k0 + t    ];
            a[2] = sm->Ps[rb + g    ][k0 + t + 4];
            a[3] = sm->Ps[rb + g + 8][k0 + t + 4];
#pragma unroll
            for (int dt = 0; dt < 8; dt++) {
                uint32_t b[2];
                b[0] = sm->Vt[dt*8 + g][k0 + t    ];
                b[1] = sm->Vt[dt*8 + g][k0 + t + 4];
                mma_tf32(oacc[dt], a, b);
            }
        }
        __syncwarp();   // PV reads of Ps done before next iteration's writes
    }

    // ---- epilogue: normalize, write to g_cat (b*S+q, 512 + h*64 + d) ----
    const int b = bh >> 3, h = bh & 7;
    const float inv0 = 1.f / l0;
    const float inv1 = 1.f / l1;
    const int q0 = qt*128 + rb + g;
    float* row0 = g_cat + (size_t)(b*NS + q0    )*1024 + 512 + h*64;
    float* row1 = g_cat + (size_t)(b*NS + q0 + 8)*1024 + 512 + h*64;
#pragma unroll
    for (int dt = 0; dt < 8; dt++) {
        float2 v0 = { oacc[dt][0] * inv0, oacc[dt][1] * inv0 };
        float2 v1 = { oacc[dt][2] * inv1, oacc[dt][3] * inv1 };
        *(float2*)(row0 + dt*8 + 2*t) = v0;
        *(float2*)(row1 + dt*8 + 2*t) = v1;
    }
}

// ---------------------------------------------------------------------------
// Kernel 3: out = cat(8192x1024) @ Wo^T + bo via mma.sync tf32 (unchanged).
// ---------------------------------------------------------------------------
__global__ void __launch_bounds__(256, 2) outproj_kernel(
    const float* __restrict__ Wo, const float* __restrict__ bo,
    float* __restrict__ out)
{
    __shared__ uint32_t As[128][36];
    __shared__ uint32_t Bs[128][36];
    const int tid  = threadIdx.x;
    const int lane = tid & 31;
    const int wid  = tid >> 5;
    const int wm   = wid >> 2;
    const int wn   = wid & 3;
    const int g    = lane >> 2;
    const int t    = lane & 3;
    const int m0   = blockIdx.x * 128;
    const int e0   = blockIdx.y * 128;

    float acc[4][4][4];
#pragma unroll
    for (int mf = 0; mf < 4; mf++)
#pragma unroll
        for (int nf = 0; nf < 4; nf++)
#pragma unroll
            for (int r = 0; r < 4; r++) acc[mf][nf][r] = 0.f;

    for (int kt = 0; kt < 32; kt++) {
        __syncthreads();
        const float* Ak = g_cat + (size_t)m0 * 1024 + kt * 32;
        const float* Bk = Wo    + (size_t)e0 * 1024 + kt * 32;
#pragma unroll
        for (int it = 0; it < 4; it++) {
            const int idx = it * 256 + tid;
            const int r = idx >> 3, c4 = (idx & 7) * 4;
            float4 a = *(const float4*)(Ak + (size_t)r * 1024 + c4);
            uint4 ua = { f2tf32(a.x), f2tf32(a.y), f2tf32(a.z), f2tf32(a.w) };
            *(uint4*)&As[r][c4] = ua;
            float4 b = *(const float4*)(Bk + (size_t)r * 1024 + c4);
            uint4 ub = { f2tf32(b.x), f2tf32(b.y), f2tf32(b.z), f2tf32(b.w) };
            *(uint4*)&Bs[r][c4] = ub;
        }
        __syncthreads();

#pragma unroll
        for (int ks = 0; ks < 4; ks++) {
            const int k0 = ks * 8;
            uint32_t a[4][4], b[4][2];
#pragma unroll
            for (int mf = 0; mf < 4; mf++) {
                const int rb2 = wm * 64 + mf * 16;
                a[mf][0] = As[rb2 + g    ][k0 + t    ];
                a[mf][1] = As[rb2 + g + 8][k0 + t    ];
                a[mf][2] = As[rb2 + g    ][k0 + t + 4];
                a[mf][3] = As[rb2 + g + 8][k0 + t + 4];
            }
#pragma unroll
            for (int nf = 0; nf < 4; nf++) {
                const int nb = wn * 32 + nf * 8;
                b[nf][0] = Bs[nb + g][k0 + t    ];
                b[nf][1] = Bs[nb + g][k0 + t + 4];
            }
#pragma unroll
            for (int mf = 0; mf < 4; mf++)
#pragma unroll
                for (int nf = 0; nf < 4; nf++)
                    mma_tf32(acc[mf][nf], a[mf], b[nf]);
        }
    }

#pragma unroll
    for (int mf = 0; mf < 4; mf++) {
        const int r0 = m0 + wm * 64 + mf * 16 + g;
#pragma unroll
        for (int nf = 0; nf < 4; nf++) {
            const int cc = e0 + wn * 32 + nf * 8 + 2 * t;
            const float b0 = bo[cc], b1 = bo[cc + 1];
            float2 v0 = { acc[mf][nf][0] + b0, acc[mf][nf][1] + b1 };
            float2 v1 = { acc[mf][nf][2] + b0, acc[mf][nf][3] + b1 };
            *(float2*)(out + (size_t)r0 * 512 + cc)       = v0;
            *(float2*)(out + (size_t)(r0 + 8) * 512 + cc) = v1;
        }
    }
}

// ---------------------------------------------------------------------------
extern "C" void kernel_launch(void* const* d_in, const int* in_sizes, int n_in,
                              void* d_out, int out_size)
{
    const float* query = (const float*)d_in[0];
    const float* key   = (const float*)d_in[1];
    const float* value = (const float*)d_in[2];
    // d_in[3]: mask (int32) — no-op in the reference
    const float* Wq_in = (const float*)d_in[4];
    const float* bq_in = (const float*)d_in[5];
    const float* Wk_in = (const float*)d_in[6];
    const float* bk_in = (const float*)d_in[7];
    const float* Wv_in = (const float*)d_in[8];
    const float* bv_in = (const float*)d_in[9];
    const float* wvq   = (const float*)d_in[10];
    const float* wvk   = (const float*)d_in[11];
    const float* wvv   = (const float*)d_in[12];
    const float* Wq_o  = (const float*)d_in[13];
    const float* bq_o  = (const float*)d_in[14];
    const float* Wk_o  = (const float*)d_in[15];
    const float* bk_o  = (const float*)d_in[16];
    const float* Wv_o  = (const float*)d_in[17];
    const float* bv_o  = (const float*)d_in[18];
    const float* Wo    = (const float*)d_in[19];
    const float* bo    = (const float*)d_in[20];
    float* out = (float*)d_out;

    cudaFuncSetAttribute(attn_kernel, cudaFuncAttributeMaxDynamicSharedMemorySize,
                         (int)sizeof(AtSmem));

    proj_kernel<<<dim3(8192, 3), 256>>>(query, key, value,
                                        Wq_in, bq_in, Wk_in, bk_in, Wv_in, bv_in,
                                        wvq, wvk, wvv,
                                        Wq_o, bq_o, Wk_o, bk_o, Wv_o, bv_o);
    attn_kernel<<<512, 256, sizeof(AtSmem)>>>();
    outproj_kernel<<<dim3(64, 4), 256>>>(Wo, bo, out);
}

// round 5
// speedup vs baseline: 3.4275x; 1.4138x over previous
#include <cuda_runtime.h>
#include <cuda_fp16.h>
#include <cstdint>

#define NB 16
#define NS 512
#define NE 512
#define NH 8
#define ND 64

// Scratch (device globals — no allocation allowed)
__device__ float g_Q[NB*NH*NS*ND];           // (b,h,s,d) 16MB
__device__ float g_K[NB*NH*NS*ND];
__device__ float g_V[NB*NH*NS*ND];
__device__ float g_cat[NB*NS*2*NE];          // (b*s, [Qf | attn_out]) 32MB

__device__ __forceinline__ uint32_t pack_h2(float lo, float hi) {
    __half2 h = __float22half2_rn(make_float2(lo, hi));
    return *(uint32_t*)&h;
}

// mma.sync m16n8k16 f16 inputs, f32 accum: D = A*B + D
__device__ __forceinline__ void mma_f16(float* c, const uint32_t* a, const uint32_t* b)
{
    asm volatile(
        "mma.sync.aligned.m16n8k16.row.col.f32.f16.f16.f32 "
        "{%0,%1,%2,%3}, {%4,%5,%6,%7}, {%8,%9}, {%0,%1,%2,%3};"
        : "+f"(c[0]), "+f"(c[1]), "+f"(c[2]), "+f"(c[3])
        : "r"(a[0]), "r"(a[1]), "r"(a[2]), "r"(a[3]), "r"(b[0]), "r"(b[1]));
}

// ---------------------------------------------------------------------------
// Kernel 1: VQC projection (unchanged, known good).
// ---------------------------------------------------------------------------
__global__ void proj_kernel(
    const float* __restrict__ Xq, const float* __restrict__ Xk, const float* __restrict__ Xv,
    const float* __restrict__ Wq_in, const float* __restrict__ bq_in,
    const float* __restrict__ Wk_in, const float* __restrict__ bk_in,
    const float* __restrict__ Wv_in, const float* __restrict__ bv_in,
    const float* __restrict__ wvq, const float* __restrict__ wvk, const float* __restrict__ wvv,
    const float* __restrict__ Wq_o, const float* __restrict__ bq_o,
    const float* __restrict__ Wk_o, const float* __restrict__ bk_o,
    const float* __restrict__ Wv_o, const float* __restrict__ bv_o)
{
    const int t = blockIdx.y;
    const float *X, *Win, *bin, *wv, *Wout, *bout;
    float* dst;
    if (t == 0)      { X=Xq; Win=Wq_in; bin=bq_in; wv=wvq; Wout=Wq_o; bout=bq_o; dst=g_Q; }
    else if (t == 1) { X=Xk; Win=Wk_in; bin=bk_in; wv=wvk; Wout=Wk_o; bout=bk_o; dst=g_K; }
    else             { X=Xv; Win=Wv_in; bin=bv_in; wv=wvv; Wout=Wv_o; bout=bv_o; dst=g_V; }

    const int lane = threadIdx.x & 31;
    const int m = blockIdx.x * 8 + (threadIdx.x >> 5);
    const float* x = X + (size_t)m * 64;
    const float x0 = x[lane];
    const float x1 = x[lane + 32];

    float c[4];
#pragma unroll
    for (int q = 0; q < 4; q++) {
        float p = x0 * Win[q*64 + lane] + x1 * Win[q*64 + 32 + lane];
#pragma unroll
        for (int off = 16; off; off >>= 1)
            p += __shfl_xor_sync(0xffffffffu, p, off);
        c[q] = __cosf(p + bin[q] + wv[q]);
    }
    const float z0 = c[1]*c[2]*c[3];
    const float z1 = c[0]*c[1];
    const float z2 = z1*c[2];
    const float z3 = z2*c[3];

    const int h  = m & 7;
    const int bs = m >> 3;
    const int b  = bs >> 9;
    const int s  = bs & 511;
    float* drow = dst + ((size_t)(b*NH + h) * NS + s) * 64;
#pragma unroll
    for (int half = 0; half < 2; half++) {
        const int d = lane + 32*half;
        const float4 w = *(const float4*)(Wout + d*4);
        const float o = z0*w.x + z1*w.y + z2*w.z + z3*w.w + bout[d];
        drow[d] = o;
        if (t == 0) g_cat[(size_t)bs*1024 + h*64 + d] = o;
    }
}

// ---------------------------------------------------------------------------
// Kernel 2: flash attention via fp16 mma.sync (m16n8k16, f32 accum).
// Block: 128 queries x one (b,h); 8 warps x 16-row strips.
// Smem rows: 64 halves = 32 words + 4 pad = 36 words (conflict-free frags).
// ---------------------------------------------------------------------------
struct AtSmem {
    uint32_t Qs[128][36];   // half2(q/32) [q][k-pair]
    uint32_t Ks[64][36];    // half2 K    [key][d-pair]
    uint32_t Vt[64][36];    // half2 V^T  [d][key-pair]
    uint32_t Ps[128][36];   // half2 P    [q][key-pair]
};

extern __shared__ unsigned char dyn_smem[];

__global__ void __launch_bounds__(256, 2) attn_kernel()
{
    AtSmem* sm = (AtSmem*)dyn_smem;
    const int tid  = threadIdx.x;
    const int lane = tid & 31;
    const int wid  = tid >> 5;
    const int g    = lane >> 2;     // 0..7
    const int t    = lane & 3;      // 0..3
    const int rb   = wid * 16;      // warp row strip
    const int qt   = blockIdx.x & 3;
    const int bh   = blockIdx.x >> 2;

    const float* Qg = g_Q + ((size_t)bh * NS + qt*128) * 64;
    const float* Kg = g_K + (size_t)bh * NS * 64;
    const float* Vg = g_V + (size_t)bh * NS * 64;

    // Q tile: 128x64, scale 1/32, fp32 -> half2
#pragma unroll
    for (int it = 0; it < 8; it++) {
        const int idx = it * 256 + tid;
        const int r = idx >> 4, c4 = (idx & 15) * 4;
        float4 v = *(const float4*)(Qg + (size_t)r * 64 + c4);
        uint2 u = { pack_h2(v.x * 0.03125f, v.y * 0.03125f),
                    pack_h2(v.z * 0.03125f, v.w * 0.03125f) };
        *(uint2*)&sm->Qs[r][(idx & 15) * 2] = u;
    }

    float m0 = -1e30f, m1 = -1e30f, l0 = 0.f, l1 = 0.f;
    float oacc[8][4];
#pragma unroll
    for (int d = 0; d < 8; d++)
#pragma unroll
        for (int r = 0; r < 4; r++) oacc[d][r] = 0.f;

    for (int kt = 0; kt < 8; kt++) {
        __syncthreads();
        const float* Kt  = Kg + kt * 64 * 64;
        const float* Vtg = Vg + kt * 64 * 64;
#pragma unroll
        for (int it = 0; it < 4; it++) {
            const int idx = it * 256 + tid;
            const int r = idx >> 4, c4 = (idx & 15) * 4;
            float4 kk = *(const float4*)(Kt + (size_t)r * 64 + c4);
            uint2 uk = { pack_h2(kk.x, kk.y), pack_h2(kk.z, kk.w) };
            *(uint2*)&sm->Ks[r][(idx & 15) * 2] = uk;
            float4 vv = *(const float4*)(Vtg + (size_t)r * 64 + c4);
            // V^T halves: Vt[d][key]; 16-bit scatter stores
            ((__half*)&sm->Vt[c4+0][0])[r] = __float2half_rn(vv.x);
            ((__half*)&sm->Vt[c4+1][0])[r] = __float2half_rn(vv.y);
            ((__half*)&sm->Vt[c4+2][0])[r] = __float2half_rn(vv.z);
            ((__half*)&sm->Vt[c4+3][0])[r] = __float2half_rn(vv.w);
        }
        __syncthreads();

        // ---- S = Q K^T : warp strip 16 x 64, 4 k-steps of 16 ----
        float sacc[8][4];
#pragma unroll
        for (int nt = 0; nt < 8; nt++)
#pragma unroll
            for (int r = 0; r < 4; r++) sacc[nt][r] = 0.f;
#pragma unroll
        for (int ks = 0; ks < 4; ks++) {
            const int k0 = ks * 8;     // word offset (16 halves)
            uint32_t a[4];
            a[0] = sm->Qs[rb + g    ][k0 + t    ];
            a[1] = sm->Qs[rb + g + 8][k0 + t    ];
            a[2] = sm->Qs[rb + g    ][k0 + t + 4];
            a[3] = sm->Qs[rb + g + 8][k0 + t + 4];
#pragma unroll
            for (int nt = 0; nt < 8; nt++) {
                uint32_t b[2];
                b[0] = sm->Ks[nt*8 + g][k0 + t    ];
                b[1] = sm->Ks[nt*8 + g][k0 + t + 4];
                mma_f16(sacc[nt], a, b);
            }
        }

        // ---- online softmax in registers (rows g and g+8) ----
        float mt0 = -1e30f, mt1 = -1e30f;
#pragma unroll
        for (int nt = 0; nt < 8; nt++) {
            mt0 = fmaxf(mt0, fmaxf(sacc[nt][0], sacc[nt][1]));
            mt1 = fmaxf(mt1, fmaxf(sacc[nt][2], sacc[nt][3]));
        }
        mt0 = fmaxf(mt0, __shfl_xor_sync(0xffffffffu, mt0, 1));
        mt0 = fmaxf(mt0, __shfl_xor_sync(0xffffffffu, mt0, 2));
        mt1 = fmaxf(mt1, __shfl_xor_sync(0xffffffffu, mt1, 1));
        mt1 = fmaxf(mt1, __shfl_xor_sync(0xffffffffu, mt1, 2));

        const float nm0 = fmaxf(m0, mt0);
        const float nm1 = fmaxf(m1, mt1);
        const float f0 = __expf(m0 - nm0);
        const float f1 = __expf(m1 - nm1);
        m0 = nm0; m1 = nm1;

        float ls0 = 0.f, ls1 = 0.f;
#pragma unroll
        for (int nt = 0; nt < 8; nt++) {
            sacc[nt][0] = __expf(sacc[nt][0] - nm0);
            sacc[nt][1] = __expf(sacc[nt][1] - nm0);
            sacc[nt][2] = __expf(sacc[nt][2] - nm1);
            sacc[nt][3] = __expf(sacc[nt][3] - nm1);
            ls0 += sacc[nt][0] + sacc[nt][1];
            ls1 += sacc[nt][2] + sacc[nt][3];
        }
        ls0 += __shfl_xor_sync(0xffffffffu, ls0, 1);
        ls0 += __shfl_xor_sync(0xffffffffu, ls0, 2);
        ls1 += __shfl_xor_sync(0xffffffffu, ls1, 1);
        ls1 += __shfl_xor_sync(0xffffffffu, ls1, 2);
        l0 = l0 * f0 + ls0;
        l1 = l1 * f1 + ls1;
#pragma unroll
        for (int d = 0; d < 8; d++) {
            oacc[d][0] *= f0; oacc[d][1] *= f0;
            oacc[d][2] *= f1; oacc[d][3] *= f1;
        }

        // stage P (warp-private rows) as half2: word (key pair) index nt*4+t
#pragma unroll
        for (int nt = 0; nt < 8; nt++) {
            sm->Ps[rb + g    ][nt*4 + t] = pack_h2(sacc[nt][0], sacc[nt][1]);
            sm->Ps[rb + g + 8][nt*4 + t] = pack_h2(sacc[nt][2], sacc[nt][3]);
        }
        __syncwarp();

        // ---- O += P V : A = P (16x64), B = Vt ----
#pragma unroll
        for (int ks = 0; ks < 4; ks++) {
            const int k0 = ks * 8;
            uint32_t a[4];
            a[0] = sm->Ps[rb + g    ][k0 + t    ];
            a[1] = sm->Ps[rb + g + 8][k0 + t    ];
            a[2] = sm->Ps[rb + g    ][k0 + t + 4];
            a[3] = sm->Ps[rb + g + 8][k0 + t + 4];
#pragma unroll
            for (int dt = 0; dt < 8; dt++) {
                uint32_t b[2];
                b[0] = sm->Vt[dt*8 + g][k0 + t    ];
                b[1] = sm->Vt[dt*8 + g][k0 + t + 4];
                mma_f16(oacc[dt], a, b);
            }
        }
        __syncwarp();   // PV reads of Ps done before next iteration's writes
    }

    // ---- epilogue: normalize, write to g_cat ----
    const int b = bh >> 3, h = bh & 7;
    const float inv0 = 1.f / l0;
    const float inv1 = 1.f / l1;
    const int q0 = qt*128 + rb + g;
    float* row0 = g_cat + (size_t)(b*NS + q0    )*1024 + 512 + h*64;
    float* row1 = g_cat + (size_t)(b*NS + q0 + 8)*1024 + 512 + h*64;
#pragma unroll
    for (int dt = 0; dt < 8; dt++) {
        float2 v0 = { oacc[dt][0] * inv0, oacc[dt][1] * inv0 };
        float2 v1 = { oacc[dt][2] * inv1, oacc[dt][3] * inv1 };
        *(float2*)(row0 + dt*8 + 2*t) = v0;
        *(float2*)(row1 + dt*8 + 2*t) = v1;
    }
}

// ---------------------------------------------------------------------------
// Kernel 3: out = cat(8192x1024) @ Wo^T + bo via fp16 mma.sync.
// 128x128 tile, 8 warps (2x4), warp 64x32; K-chunks of 64 (4 k16 steps).
// ---------------------------------------------------------------------------
__global__ void __launch_bounds__(256, 2) outproj_kernel(
    const float* __restrict__ Wo, const float* __restrict__ bo,
    float* __restrict__ out)
{
    __shared__ uint32_t As[128][36];   // half2 [m][k-pair]
    __shared__ uint32_t Bs[128][36];   // half2 [n][k-pair]
    const int tid  = threadIdx.x;
    const int lane = tid & 31;
    const int wid  = tid >> 5;
    const int wm   = wid >> 2;
    const int wn   = wid & 3;
    const int g    = lane >> 2;
    const int t    = lane & 3;
    const int m0   = blockIdx.x * 128;
    const int e0   = blockIdx.y * 128;

    float acc[4][4][4];
#pragma unroll
    for (int mf = 0; mf < 4; mf++)
#pragma unroll
        for (int nf = 0; nf < 4; nf++)
#pragma unroll
            for (int r = 0; r < 4; r++) acc[mf][nf][r] = 0.f;

    for (int kt = 0; kt < 16; kt++) {
        __syncthreads();
        const float* Ak = g_cat + (size_t)m0 * 1024 + kt * 64;
        const float* Bk = Wo    + (size_t)e0 * 1024 + kt * 64;
#pragma unroll
        for (int it = 0; it < 8; it++) {
            const int idx = it * 256 + tid;          // 2048 float4 per tile
            const int r = idx >> 4, c4 = (idx & 15) * 4;
            float4 a = *(const float4*)(Ak + (size_t)r * 1024 + c4);
            uint2 ua = { pack_h2(a.x, a.y), pack_h2(a.z, a.w) };
            *(uint2*)&As[r][(idx & 15) * 2] = ua;
            float4 b = *(const float4*)(Bk + (size_t)r * 1024 + c4);
            uint2 ub = { pack_h2(b.x, b.y), pack_h2(b.z, b.w) };
            *(uint2*)&Bs[r][(idx & 15) * 2] = ub;
        }
        __syncthreads();

#pragma unroll
        for (int ks = 0; ks < 4; ks++) {
            const int k0 = ks * 8;
            uint32_t a[4][4], b[4][2];
#pragma unroll
            for (int mf = 0; mf < 4; mf++) {
                const int rb2 = wm * 64 + mf * 16;
                a[mf][0] = As[rb2 + g    ][k0 + t    ];
                a[mf][1] = As[rb2 + g + 8][k0 + t    ];
                a[mf][2] = As[rb2 + g    ][k0 + t + 4];
                a[mf][3] = As[rb2 + g + 8][k0 + t + 4];
            }
#pragma unroll
            for (int nf = 0; nf < 4; nf++) {
                const int nb = wn * 32 + nf * 8;
                b[nf][0] = Bs[nb + g][k0 + t    ];
                b[nf][1] = Bs[nb + g][k0 + t + 4];
            }
#pragma unroll
            for (int mf = 0; mf < 4; mf++)
#pragma unroll
                for (int nf = 0; nf < 4; nf++)
                    mma_f16(acc[mf][nf], a[mf], b[nf]);
        }
    }

#pragma unroll
    for (int mf = 0; mf < 4; mf++) {
        const int r0 = m0 + wm * 64 + mf * 16 + g;
#pragma unroll
        for (int nf = 0; nf < 4; nf++) {
            const int cc = e0 + wn * 32 + nf * 8 + 2 * t;
            const float b0 = bo[cc], b1 = bo[cc + 1];
            float2 v0 = { acc[mf][nf][0] + b0, acc[mf][nf][1] + b1 };
            float2 v1 = { acc[mf][nf][2] + b0, acc[mf][nf][3] + b1 };
            *(float2*)(out + (size_t)r0 * 512 + cc)       = v0;
            *(float2*)(out + (size_t)(r0 + 8) * 512 + cc) = v1;
        }
    }
}

// ---------------------------------------------------------------------------
extern "C" void kernel_launch(void* const* d_in, const int* in_sizes, int n_in,
                              void* d_out, int out_size)
{
    const float* query = (const float*)d_in[0];
    const float* key   = (const float*)d_in[1];
    const float* value = (const float*)d_in[2];
    // d_in[3]: mask (int32) — no-op in the reference
    const float* Wq_in = (const float*)d_in[4];
    const float* bq_in = (const float*)d_in[5];
    const float* Wk_in = (const float*)d_in[6];
    const float* bk_in = (const float*)d_in[7];
    const float* Wv_in = (const float*)d_in[8];
    const float* bv_in = (const float*)d_in[9];
    const float* wvq   = (const float*)d_in[10];
    const float* wvk   = (const float*)d_in[11];
    const float* wvv   = (const float*)d_in[12];
    const float* Wq_o  = (const float*)d_in[13];
    const float* bq_o  = (const float*)d_in[14];
    const float* Wk_o  = (const float*)d_in[15];
    const float* bk_o  = (const float*)d_in[16];
    const float* Wv_o  = (const float*)d_in[17];
    const float* bv_o  = (const float*)d_in[18];
    const float* Wo    = (const float*)d_in[19];
    const float* bo    = (const float*)d_in[20];
    float* out = (float*)d_out;

    cudaFuncSetAttribute(attn_kernel, cudaFuncAttributeMaxDynamicSharedMemorySize,
                         (int)sizeof(AtSmem));

    proj_kernel<<<dim3(8192, 3), 256>>>(query, key, value,
                                        Wq_in, bq_in, Wk_in, bk_in, Wv_in, bv_in,
                                        wvq, wvk, wvv,
                                        Wq_o, bq_o, Wk_o, bk_o, Wv_o, bv_o);
    attn_kernel<<<512, 256, sizeof(AtSmem)>>>();
    outproj_kernel<<<dim3(64, 4), 256>>>(Wo, bo, out);
}